// round 5
// baseline (speedup 1.0000x reference)
#include <cuda_runtime.h>

// Problem constants (GATBackbone: N=50000 nodes, E=800000 edges, D=C=128, H=1)
#define NMAX 50000
#define EMAX 800000
constexpr int DDIM = 128;
constexpr int CDIM = 128;

// ---- static device scratch (no allocation allowed) ----
__device__ float g_xl[(size_t)NMAX * CDIM];   // per-layer transformed features
__device__ float g_h[(size_t)NMAX * CDIM];    // layer-1 output
__device__ float g_as[NMAX];                  // a_src per node
__device__ float g_ad[NMAX];                  // a_dst per node
__device__ int   g_deg[NMAX];
__device__ int   g_rowptr[NMAX + 1];
__device__ int   g_cursor[NMAX];
__device__ int   g_csrsrc[EMAX + NMAX];       // CSR (by dst) src indices, incl. self loops

// ============================================================================
// CSR build (shared by both layers; rebuilt every call for determinism rules)
// ============================================================================

__global__ void zero_deg_kernel(int n) {
    int i = blockIdx.x * blockDim.x + threadIdx.x;
    if (i < n) g_deg[i] = 0;
}

// edge_index is (2,E) int32 row-major: src = ei[0..E), dst = ei[E..2E).
// Items [E, E+n) are the implicit self loops.
__global__ void count_deg_kernel(const int* __restrict__ ei, int E, int n) {
    int i = blockIdx.x * blockDim.x + threadIdx.x;
    if (i < E) {
        atomicAdd(&g_deg[ei[E + i]], 1);
    } else if (i < E + n) {
        atomicAdd(&g_deg[i - E], 1);
    }
}

// Single-block exclusive scan: each thread serial-scans a contiguous chunk,
// block-scan of the 1024 chunk sums, then second serial pass writes rowptr+cursor.
__global__ void scan_deg_kernel(int n) {
    __shared__ int sums[1024];
    int t = threadIdx.x;
    int chunk = (n + 1023) >> 10;
    int b = t * chunk;
    int e = min(b + chunk, n);
    int s = 0;
    for (int i = b; i < e; i++) s += g_deg[i];
    sums[t] = s;
    __syncthreads();
    // Hillis-Steele inclusive scan over 1024 partial sums
    for (int off = 1; off < 1024; off <<= 1) {
        int v = (t >= off) ? sums[t - off] : 0;
        __syncthreads();
        sums[t] += v;
        __syncthreads();
    }
    int run = sums[t] - s;  // exclusive prefix for this chunk
    for (int i = b; i < e; i++) {
        g_rowptr[i] = run;
        g_cursor[i] = run;
        run += g_deg[i];
    }
    if (t == 1023) g_rowptr[n] = sums[1023];
}

__global__ void scatter_edges_kernel(const int* __restrict__ ei, int E, int n) {
    int i = blockIdx.x * blockDim.x + threadIdx.x;
    if (i < E) {
        int s = ei[i];
        int d = ei[E + i];
        g_csrsrc[atomicAdd(&g_cursor[d], 1)] = s;
    } else if (i < E + n) {
        int v = i - E;
        g_csrsrc[atomicAdd(&g_cursor[v], 1)] = v;
    }
}

// ============================================================================
// Fused GEMM + attention coefficients:
//   XL = X @ W  (NxD @ DxC, D=C=128), a_s[i] = dot(XL[i], att_src),
//   a_d[i] = dot(XL[i], att_dst).
// Block = 256 threads, 32 rows/block (4 rows/warp). W tiled over k in 2 halves
// (32 KB smem each) + 16 KB X tile = 48 KB static smem.
// ============================================================================
__global__ __launch_bounds__(256) void gemm_attn_kernel(
    const float* __restrict__ X, const float* __restrict__ W,
    const float* __restrict__ atts, const float* __restrict__ attd,
    float* __restrict__ XL, int n)
{
    __shared__ float Wsh[64 * 128];   // 32 KB: 64 k-rows of W
    __shared__ float Xsh[32 * 128];   // 16 KB: 32 rows of X

    int t = threadIdx.x;
    int lane = t & 31;
    int warp = t >> 5;
    int row0 = blockIdx.x * 32;

    // Load X tile (zero-pad past n)
    const float4* X4 = (const float4*)X;
    float4* Xsh4 = (float4*)Xsh;
#pragma unroll
    for (int i = 0; i < 4; i++) {
        int idx = t + i * 256;          // [0, 1024)
        int r = idx >> 5;
        float4 v = make_float4(0.f, 0.f, 0.f, 0.f);
        if (row0 + r < n) v = X4[(size_t)(row0 + r) * 32 + (idx & 31)];
        Xsh4[idx] = v;
    }

    float4 acc[4];
#pragma unroll
    for (int r = 0; r < 4; r++) acc[r] = make_float4(0.f, 0.f, 0.f, 0.f);

    const float4* W4 = (const float4*)W;
    float4* Wsh4 = (float4*)Wsh;
    const int rbase = warp * 4;

    for (int kh = 0; kh < 2; kh++) {
        __syncthreads();  // also covers Xsh writes on first iteration
#pragma unroll
        for (int i = 0; i < 8; i++) Wsh4[t + i * 256] = W4[kh * 2048 + t + i * 256];
        __syncthreads();
#pragma unroll 8
        for (int k = 0; k < 64; k++) {
            float4 wv = ((const float4*)Wsh)[k * 32 + lane];
#pragma unroll
            for (int r = 0; r < 4; r++) {
                float xv = Xsh[(rbase + r) * 128 + kh * 64 + k];  // broadcast LDS
                acc[r].x = fmaf(xv, wv.x, acc[r].x);
                acc[r].y = fmaf(xv, wv.y, acc[r].y);
                acc[r].z = fmaf(xv, wv.z, acc[r].z);
                acc[r].w = fmaf(xv, wv.w, acc[r].w);
            }
        }
    }

    // Epilogue: store XL and compute attention dot products with warp reduce.
    float4 sv = ((const float4*)atts)[lane];
    float4 dv = ((const float4*)attd)[lane];
#pragma unroll
    for (int r = 0; r < 4; r++) {
        int row = row0 + rbase + r;
        if (row < n) {
            ((float4*)XL)[(size_t)row * 32 + lane] = acc[r];
            float ps = acc[r].x * sv.x + acc[r].y * sv.y + acc[r].z * sv.z + acc[r].w * sv.w;
            float pd = acc[r].x * dv.x + acc[r].y * dv.y + acc[r].z * dv.z + acc[r].w * dv.w;
#pragma unroll
            for (int off = 16; off; off >>= 1) {
                ps += __shfl_xor_sync(0xffffffffu, ps, off);
                pd += __shfl_xor_sync(0xffffffffu, pd, off);
            }
            if (lane == 0) { g_as[row] = ps; g_ad[row] = pd; }
        }
    }
}

// ============================================================================
// Aggregation: one warp per dst node v.
//   w_e = exp(leakyrelu(a_s[src]+a_d[v]));  out[v] = relu(Σ w_e·XL[src] / Σ w_e + b)
// (unnormalized-softmax form; mathematically identical to max-subtracted ref)
// Each lane owns 4 channels (float4). exp computed once per edge, shfl-broadcast.
// ============================================================================
__global__ __launch_bounds__(256) void aggregate_kernel(
    const float* __restrict__ XL,
    const float* __restrict__ bias,
    float* __restrict__ OUT, int n)
{
    int wid = (int)((blockIdx.x * (unsigned)blockDim.x + threadIdx.x) >> 5);
    int lane = threadIdx.x & 31;
    if (wid >= n) return;

    int beg = g_rowptr[wid];
    int end = g_rowptr[wid + 1];
    float adv = g_ad[wid];

    float4 acc = make_float4(0.f, 0.f, 0.f, 0.f);
    float z = 0.f;
    const float4* XL4 = (const float4*)XL;

    for (int e0 = beg; e0 < end; e0 += 32) {
        int i = e0 + lane;
        int s = 0;
        float w = 0.f;
        if (i < end) {
            s = g_csrsrc[i];
            float tv = g_as[s] + adv;
            tv = tv > 0.f ? tv : 0.2f * tv;    // leaky_relu(0.2)
            w = __expf(tv);
        }
        int cnt = min(32, end - e0);
        for (int j = 0; j < cnt; j++) {
            float wj = __shfl_sync(0xffffffffu, w, j);
            int   sj = __shfl_sync(0xffffffffu, s, j);
            float4 xv = XL4[(size_t)sj * 32 + lane];
            acc.x = fmaf(wj, xv.x, acc.x);
            acc.y = fmaf(wj, xv.y, acc.y);
            acc.z = fmaf(wj, xv.z, acc.z);
            acc.w = fmaf(wj, xv.w, acc.w);
            z += wj;
        }
    }

    float inv = 1.f / (z + 1e-16f);
    float4 bv = ((const float4*)bias)[lane];
    float4 o;
    o.x = fmaxf(fmaf(acc.x, inv, bv.x), 0.f);
    o.y = fmaxf(fmaf(acc.y, inv, bv.y), 0.f);
    o.z = fmaxf(fmaf(acc.z, inv, bv.z), 0.f);
    o.w = fmaxf(fmaf(acc.w, inv, bv.w), 0.f);
    ((float4*)OUT)[(size_t)wid * 32 + lane] = o;
}

// ============================================================================
// Launch
// ============================================================================
extern "C" void kernel_launch(void* const* d_in, const int* in_sizes, int n_in,
                              void* d_out, int out_size)
{
    const float* x   = (const float*)d_in[0];
    const int*   ei  = (const int*)d_in[1];
    const float* W1  = (const float*)d_in[2];
    const float* as1 = (const float*)d_in[3];
    const float* ad1 = (const float*)d_in[4];
    const float* b1  = (const float*)d_in[5];
    const float* W2  = (const float*)d_in[6];
    const float* as2 = (const float*)d_in[7];
    const float* ad2 = (const float*)d_in[8];
    const float* b2  = (const float*)d_in[9];

    int n = in_sizes[0] / DDIM;   // 50000
    int E = in_sizes[1] / 2;      // 800000
    float* out = (float*)d_out;

    void* xl_p = nullptr;
    void* h_p  = nullptr;
    cudaGetSymbolAddress(&xl_p, g_xl);
    cudaGetSymbolAddress(&h_p,  g_h);
    float* xl = (float*)xl_p;
    float* h  = (float*)h_p;

    // --- CSR build (by dst, with self loops) ---
    int ee = E + n;
    zero_deg_kernel<<<(n + 255) / 256, 256>>>(n);
    count_deg_kernel<<<(ee + 255) / 256, 256>>>(ei, E, n);
    scan_deg_kernel<<<1, 1024>>>(n);
    scatter_edges_kernel<<<(ee + 255) / 256, 256>>>(ei, E, n);

    // --- Layer 1 ---
    gemm_attn_kernel<<<(n + 31) / 32, 256>>>(x, W1, as1, ad1, xl, n);
    aggregate_kernel<<<(n + 7) / 8, 256>>>(xl, b1, h, n);

    // --- Layer 2 ---
    gemm_attn_kernel<<<(n + 31) / 32, 256>>>(h, W2, as2, ad2, xl, n);
    aggregate_kernel<<<(n + 7) / 8, 256>>>(xl, b2, out, n);
}

// round 7
// speedup vs baseline: 1.5045x; 1.5045x over previous
#include <cuda_runtime.h>
#include <cstdint>

// Problem constants: N=50000 nodes, E=800000 edges, D=C=128, H=1
#define NMAX 50000
#define EMAX 800000
#define EE   (EMAX + NMAX)
constexpr int DDIM = 128;

constexpr int XS_STRIDE = 132;   // X smem pad: bank = (4*gid + tig) = lane  -> conflict-free
constexpr int WS_STRIDE = 136;   // W smem pad: bank = (8*tig + gid)         -> conflict-free
constexpr int WIMG = 128 * WS_STRIDE;  // 17408 floats per W image

// ---------------- static device scratch ----------------
__device__ float g_xl[(size_t)NMAX * 128];
__device__ float g_h [(size_t)NMAX * 128];
__device__ float g_as[NMAX];
__device__ float g_ad[NMAX];
__device__ int   g_deg[NMAX];
__device__ int   g_rowptr[NMAX + 1];
__device__ int   g_cursor[NMAX];
__device__ int   g_csrsrc[EE];
__device__ int   g_csrdst[EE];
__device__ float g_w[EE];
__device__ int   g_bsum[256];
__device__ int   g_boff[256];
// W (per layer) as tf32-rounded hi/lo fp32, [k][n] with pad stride WS_STRIDE
__device__ __align__(16) float g_whi[2][WIMG];
__device__ __align__(16) float g_wlo[2][WIMG];

// ---------------- helpers ----------------
__device__ __forceinline__ uint32_t f2tf32(float v) {
    uint32_t u;
    asm("cvt.rna.tf32.f32 %0, %1;" : "=r"(u) : "f"(v));
    return u;
}
__device__ __forceinline__ void mma_tf32(float c[4], const uint32_t a[4], uint32_t b0, uint32_t b1) {
    asm volatile(
        "mma.sync.aligned.m16n8k8.row.col.f32.tf32.tf32.f32 "
        "{%0,%1,%2,%3}, {%4,%5,%6,%7}, {%8,%9}, {%0,%1,%2,%3};"
        : "+f"(c[0]), "+f"(c[1]), "+f"(c[2]), "+f"(c[3])
        : "r"(a[0]), "r"(a[1]), "r"(a[2]), "r"(a[3]), "r"(b0), "r"(b1));
}

// ============================================================================
// CSR build
// ============================================================================
__global__ void zero_deg_kernel(int n) {
    int i = blockIdx.x * blockDim.x + threadIdx.x;
    if (i < n) g_deg[i] = 0;
}
__global__ void count_deg_kernel(const int* __restrict__ ei, int E, int n) {
    int i = blockIdx.x * blockDim.x + threadIdx.x;
    if (i < E)           atomicAdd(&g_deg[ei[E + i]], 1);
    else if (i < E + n)  atomicAdd(&g_deg[i - E], 1);
}
__global__ void block_sum_kernel(int n) {
    __shared__ int sh[256];
    int t = threadIdx.x;
    int i = blockIdx.x * 256 + t;
    sh[t] = (i < n) ? g_deg[i] : 0;
    __syncthreads();
    for (int o = 128; o; o >>= 1) { if (t < o) sh[t] += sh[t + o]; __syncthreads(); }
    if (t == 0) g_bsum[blockIdx.x] = sh[0];
}
__global__ void scan_bsum_kernel(int nb) {
    __shared__ int sh[256];
    int t = threadIdx.x;
    int v = (t < nb) ? g_bsum[t] : 0;
    sh[t] = v;
    __syncthreads();
    for (int o = 1; o < 256; o <<= 1) {
        int u = (t >= o) ? sh[t - o] : 0;
        __syncthreads();
        sh[t] += u;
        __syncthreads();
    }
    g_boff[t] = sh[t] - v;  // exclusive
}
__global__ void write_rowptr_kernel(int n) {
    __shared__ int sh[256];
    int t = threadIdx.x;
    int i = blockIdx.x * 256 + t;
    int v = (i < n) ? g_deg[i] : 0;
    sh[t] = v;
    __syncthreads();
    for (int o = 1; o < 256; o <<= 1) {
        int u = (t >= o) ? sh[t - o] : 0;
        __syncthreads();
        sh[t] += u;
        __syncthreads();
    }
    int excl = sh[t] - v + g_boff[blockIdx.x];
    if (i < n) {
        g_rowptr[i] = excl;
        g_cursor[i] = excl;
        if (i == n - 1) g_rowptr[n] = excl + v;
    }
}
__global__ void scatter_edges_kernel(const int* __restrict__ ei, int E, int n) {
    int i = blockIdx.x * blockDim.x + threadIdx.x;
    if (i < E) {
        int s = ei[i];
        int d = ei[E + i];
        int p = atomicAdd(&g_cursor[d], 1);
        g_csrsrc[p] = s;
        g_csrdst[p] = d;
    } else if (i < E + n) {
        int v = i - E;
        int p = atomicAdd(&g_cursor[v], 1);
        g_csrsrc[p] = v;
        g_csrdst[p] = v;
    }
}

// ============================================================================
// W -> tf32 hi/lo images ([k][n], pad stride 136), both layers
// ============================================================================
__global__ void wprep_kernel(const float* __restrict__ W1, const float* __restrict__ W2) {
    int t = blockIdx.x * 256 + threadIdx.x;   // 0..32767
    int layer = t >> 14;
    int idx = t & 16383;                      // k*128 + n (coalesced read)
    int k = idx >> 7, nn = idx & 127;
    float v = (layer ? W2 : W1)[idx];
    uint32_t hi = f2tf32(v);
    float lo_f = v - __uint_as_float(hi);
    uint32_t lo = f2tf32(lo_f);
    g_whi[layer][k * WS_STRIDE + nn] = __uint_as_float(hi);
    g_wlo[layer][k * WS_STRIDE + nn] = __uint_as_float(lo);
}

// ============================================================================
// Tensor-core GEMM + attention: XL = X @ W via tf32-split mma.sync (3 passes),
// fused a_s/a_d epilogue. CTA = 128 rows, 8 warps (16 rows/warp).
// ============================================================================
constexpr uint32_t SMEM_FLOATS = 128 * XS_STRIDE + 2 * WIMG;   // 51712
constexpr uint32_t SMEM_BYTES  = SMEM_FLOATS * 4;              // 206848

__global__ __launch_bounds__(256) void gemm_mma_kernel(
    const float* __restrict__ X,
    const float* __restrict__ Whi, const float* __restrict__ Wlo,
    const float* __restrict__ atts, const float* __restrict__ attd,
    float* __restrict__ XL, int n)
{
    extern __shared__ float sm[];
    float* Xs = sm;                       // 128 x 132
    float* Wh = sm + 128 * XS_STRIDE;     // 128 x 136
    float* Wl = Wh + WIMG;

    int tid = threadIdx.x, lane = tid & 31, warp = tid >> 5;
    int gid = lane >> 2, tig = lane & 3;
    int row0 = blockIdx.x * 128;

    // W tiles: linear float4 copies of the padded images (L2-broadcast across CTAs)
    {
        const float4* gh = (const float4*)Whi;
        const float4* gl = (const float4*)Wlo;
        float4* sh = (float4*)Wh;
        float4* sl = (float4*)Wl;
#pragma unroll
        for (int i = 0; i < 17; i++) {
            int idx = tid + i * 256;
            if (idx < WIMG / 4) { sh[idx] = gh[idx]; sl[idx] = gl[idx]; }
        }
    }
    // X tile: coalesced float4 loads, padded-stride stores (row start 528B, 16B aligned)
    {
        const float4* X4 = (const float4*)X;
#pragma unroll
        for (int i = 0; i < 16; i++) {
            int idx = tid + i * 256;        // 128 rows x 32 float4
            int r = idx >> 5, c = idx & 31;
            float4 v = make_float4(0.f, 0.f, 0.f, 0.f);
            if (row0 + r < n) v = X4[(size_t)(row0 + r) * 32 + c];
            *(float4*)(Xs + r * XS_STRIDE + c * 4) = v;
        }
    }
    __syncthreads();

    const int rbase = warp * 16;
    float c[16][4];
#pragma unroll
    for (int nt = 0; nt < 16; nt++) { c[nt][0] = c[nt][1] = c[nt][2] = c[nt][3] = 0.f; }

    const float* xr0 = Xs + (rbase + gid) * XS_STRIDE + tig;
    const float* xr1 = xr0 + 8 * XS_STRIDE;

    for (int ks = 0; ks < 16; ks++) {
        int k0 = ks * 8;
        // A fragments (hi/lo tf32 split, computed once per k-step)
        float x0 = xr0[k0], x1 = xr1[k0], x2 = xr0[k0 + 4], x3 = xr1[k0 + 4];
        uint32_t ah[4], al[4];
        ah[0] = f2tf32(x0); al[0] = f2tf32(x0 - __uint_as_float(ah[0]));
        ah[1] = f2tf32(x1); al[1] = f2tf32(x1 - __uint_as_float(ah[1]));
        ah[2] = f2tf32(x2); al[2] = f2tf32(x2 - __uint_as_float(ah[2]));
        ah[3] = f2tf32(x3); al[3] = f2tf32(x3 - __uint_as_float(ah[3]));

        const float* wh0 = Wh + (k0 + tig) * WS_STRIDE + gid;
        const float* wl0 = Wl + (k0 + tig) * WS_STRIDE + gid;
#pragma unroll
        for (int nt = 0; nt < 16; nt++) {
            int nb = nt * 8;
            uint32_t bh0 = __float_as_uint(wh0[nb]);
            uint32_t bh1 = __float_as_uint(wh0[nb + 4 * WS_STRIDE]);
            uint32_t bl0 = __float_as_uint(wl0[nb]);
            uint32_t bl1 = __float_as_uint(wl0[nb + 4 * WS_STRIDE]);
            mma_tf32(c[nt], ah, bh0, bh1);
            mma_tf32(c[nt], ah, bl0, bl1);
            mma_tf32(c[nt], al, bh0, bh1);
        }
    }

    // Epilogue: attention dots + stores.
    // Thread holds rows (rbase+gid, rbase+gid+8), cols nt*8 + tig*2 + {0,1}.
    float ps0 = 0.f, pd0 = 0.f, ps1 = 0.f, pd1 = 0.f;
#pragma unroll
    for (int nt = 0; nt < 16; nt++) {
        int col = nt * 8 + tig * 2;
        float a0 = __ldg(atts + col), a1 = __ldg(atts + col + 1);
        float d0 = __ldg(attd + col), d1 = __ldg(attd + col + 1);
        ps0 = fmaf(c[nt][0], a0, fmaf(c[nt][1], a1, ps0));
        pd0 = fmaf(c[nt][0], d0, fmaf(c[nt][1], d1, pd0));
        ps1 = fmaf(c[nt][2], a0, fmaf(c[nt][3], a1, ps1));
        pd1 = fmaf(c[nt][2], d0, fmaf(c[nt][3], d1, pd1));
    }
#pragma unroll
    for (int o = 1; o <= 2; o <<= 1) {
        ps0 += __shfl_xor_sync(0xffffffffu, ps0, o);
        pd0 += __shfl_xor_sync(0xffffffffu, pd0, o);
        ps1 += __shfl_xor_sync(0xffffffffu, ps1, o);
        pd1 += __shfl_xor_sync(0xffffffffu, pd1, o);
    }
    int r0 = row0 + rbase + gid;
    int r1 = r0 + 8;
    if (tig == 0) {
        if (r0 < n) { g_as[r0] = ps0; g_ad[r0] = pd0; }
        if (r1 < n) { g_as[r1] = ps1; g_ad[r1] = pd1; }
    }
    if (r0 < n) {
        float* dst = XL + (size_t)r0 * 128 + tig * 2;
#pragma unroll
        for (int nt = 0; nt < 16; nt++)
            *(float2*)(dst + nt * 8) = make_float2(c[nt][0], c[nt][1]);
    }
    if (r1 < n) {
        float* dst = XL + (size_t)r1 * 128 + tig * 2;
#pragma unroll
        for (int nt = 0; nt < 16; nt++)
            *(float2*)(dst + nt * 8) = make_float2(c[nt][2], c[nt][3]);
    }
}

// ============================================================================
// Per-edge softmax weights (CSR order): w = exp(leakyrelu(a_s[src] + a_d[dst]))
// ============================================================================
__global__ void edge_w_kernel(int ee) {
    int i = blockIdx.x * blockDim.x + threadIdx.x;
    if (i >= ee) return;
    float t = g_as[g_csrsrc[i]] + g_ad[g_csrdst[i]];
    t = t > 0.f ? t : 0.2f * t;
    g_w[i] = __expf(t);
}

// ============================================================================
// Aggregation: one warp per dst node, warp-uniform (src,w) loads, 4x unrolled.
//   out[v] = relu( (sum_e w_e * XL[src_e]) / (sum_e w_e + 1e-16) + b )
// ============================================================================
__global__ __launch_bounds__(256) void aggregate_kernel(
    const float* __restrict__ XL, const float* __restrict__ bias,
    float* __restrict__ OUT, int n)
{
    int wid = blockIdx.x * 8 + (threadIdx.x >> 5);
    int lane = threadIdx.x & 31;
    if (wid >= n) return;

    int beg = g_rowptr[wid];
    int end = g_rowptr[wid + 1];
    float4 acc = make_float4(0.f, 0.f, 0.f, 0.f);
    float z = 0.f;
    const float4* XL4 = (const float4*)XL;

    int j = beg;
    for (; j + 4 <= end; j += 4) {
        int s0 = g_csrsrc[j],     s1 = g_csrsrc[j + 1];
        int s2 = g_csrsrc[j + 2], s3 = g_csrsrc[j + 3];
        float w0 = g_w[j],     w1 = g_w[j + 1];
        float w2 = g_w[j + 2], w3 = g_w[j + 3];
        float4 x0 = XL4[(size_t)s0 * 32 + lane];
        float4 x1 = XL4[(size_t)s1 * 32 + lane];
        float4 x2 = XL4[(size_t)s2 * 32 + lane];
        float4 x3 = XL4[(size_t)s3 * 32 + lane];
        acc.x = fmaf(w0, x0.x, acc.x); acc.y = fmaf(w0, x0.y, acc.y);
        acc.z = fmaf(w0, x0.z, acc.z); acc.w = fmaf(w0, x0.w, acc.w);
        acc.x = fmaf(w1, x1.x, acc.x); acc.y = fmaf(w1, x1.y, acc.y);
        acc.z = fmaf(w1, x1.z, acc.z); acc.w = fmaf(w1, x1.w, acc.w);
        acc.x = fmaf(w2, x2.x, acc.x); acc.y = fmaf(w2, x2.y, acc.y);
        acc.z = fmaf(w2, x2.z, acc.z); acc.w = fmaf(w2, x2.w, acc.w);
        acc.x = fmaf(w3, x3.x, acc.x); acc.y = fmaf(w3, x3.y, acc.y);
        acc.z = fmaf(w3, x3.z, acc.z); acc.w = fmaf(w3, x3.w, acc.w);
        z += (w0 + w1) + (w2 + w3);
    }
    for (; j < end; j++) {
        int s = g_csrsrc[j];
        float w = g_w[j];
        float4 xv = XL4[(size_t)s * 32 + lane];
        acc.x = fmaf(w, xv.x, acc.x); acc.y = fmaf(w, xv.y, acc.y);
        acc.z = fmaf(w, xv.z, acc.z); acc.w = fmaf(w, xv.w, acc.w);
        z += w;
    }

    float inv = 1.f / (z + 1e-16f);
    float4 bv = ((const float4*)bias)[lane];
    float4 o;
    o.x = fmaxf(fmaf(acc.x, inv, bv.x), 0.f);
    o.y = fmaxf(fmaf(acc.y, inv, bv.y), 0.f);
    o.z = fmaxf(fmaf(acc.z, inv, bv.z), 0.f);
    o.w = fmaxf(fmaf(acc.w, inv, bv.w), 0.f);
    ((float4*)OUT)[(size_t)wid * 32 + lane] = o;
}

// ============================================================================
// Launch
// ============================================================================
extern "C" void kernel_launch(void* const* d_in, const int* in_sizes, int n_in,
                              void* d_out, int out_size)
{
    const float* x   = (const float*)d_in[0];
    const int*   ei  = (const int*)d_in[1];
    const float* W1  = (const float*)d_in[2];
    const float* as1 = (const float*)d_in[3];
    const float* ad1 = (const float*)d_in[4];
    const float* b1  = (const float*)d_in[5];
    const float* W2  = (const float*)d_in[6];
    const float* as2 = (const float*)d_in[7];
    const float* ad2 = (const float*)d_in[8];
    const float* b2  = (const float*)d_in[9];

    int n = in_sizes[0] / DDIM;   // 50000
    int E = in_sizes[1] / 2;      // 800000
    int ee = E + n;
    float* out = (float*)d_out;

    void *xl_p, *h_p, *wh_p, *wl_p;
    cudaGetSymbolAddress(&xl_p, g_xl);
    cudaGetSymbolAddress(&h_p,  g_h);
    cudaGetSymbolAddress(&wh_p, g_whi);
    cudaGetSymbolAddress(&wl_p, g_wlo);
    float* xl = (float*)xl_p;
    float* h  = (float*)h_p;
    const float* whi = (const float*)wh_p;
    const float* wlo = (const float*)wl_p;

    cudaFuncSetAttribute(gemm_mma_kernel, cudaFuncAttributeMaxDynamicSharedMemorySize, SMEM_BYTES);

    int nb = (n + 255) / 256;

    // --- CSR build ---
    zero_deg_kernel<<<(n + 255) / 256, 256>>>(n);
    count_deg_kernel<<<(ee + 255) / 256, 256>>>(ei, E, n);
    block_sum_kernel<<<nb, 256>>>(n);
    scan_bsum_kernel<<<1, 256>>>(nb);
    write_rowptr_kernel<<<nb, 256>>>(n);
    scatter_edges_kernel<<<(ee + 255) / 256, 256>>>(ei, E, n);

    // --- weight images ---
    wprep_kernel<<<128, 256>>>(W1, W2);

    int gblocks = (n + 127) / 128;

    // --- Layer 1 ---
    gemm_mma_kernel<<<gblocks, 256, SMEM_BYTES>>>(x, whi, wlo, as1, ad1, xl, n);
    edge_w_kernel<<<(ee + 255) / 256, 256>>>(ee);
    aggregate_kernel<<<(n + 7) / 8, 256>>>(xl, b1, h, n);

    // --- Layer 2 ---
    gemm_mma_kernel<<<gblocks, 256, SMEM_BYTES>>>(h, whi + WIMG, wlo + WIMG, as2, ad2, xl, n);
    edge_w_kernel<<<(ee + 255) / 256, 256>>>(ee);
    aggregate_kernel<<<(n + 7) / 8, 256>>>(xl, b2, out, n);
}

// round 8
// speedup vs baseline: 1.5709x; 1.0441x over previous
#include <cuda_runtime.h>
#include <cstdint>

// Problem constants: N=50000 nodes, E=800000 edges, D=C=128, H=1
#define NMAX 50000
#define EMAX 800000
#define EE   (EMAX + NMAX)
constexpr int DDIM = 128;

constexpr int XS_STRIDE = 132;   // X smem pad: bank = (4*gid + tig) = lane  -> conflict-free
constexpr int WS_STRIDE = 136;   // W smem pad: bank = (8*tig + gid)         -> conflict-free
constexpr int WIMG = 128 * WS_STRIDE;  // 17408 floats per W image
constexpr int SCAN_FLAG = 1 << 30;

// ---------------- static device scratch ----------------
__device__ float g_xl[(size_t)NMAX * 128];
__device__ float g_h [(size_t)NMAX * 128];
__device__ float g_as[NMAX];
__device__ float g_ad[NMAX];
__device__ int   g_deg[NMAX];
__device__ int   g_rowptr[NMAX + 1];
__device__ int   g_cursor[NMAX];
__device__ int   g_csrsrc[EE];
__device__ int   g_bsum[256];
// W (per layer) as tf32-rounded hi/lo fp32, [k][n] with pad stride WS_STRIDE
__device__ __align__(16) float g_whi[2][WIMG];
__device__ __align__(16) float g_wlo[2][WIMG];

// ---------------- helpers ----------------
__device__ __forceinline__ uint32_t f2tf32(float v) {
    uint32_t u;
    asm("cvt.rna.tf32.f32 %0, %1;" : "=r"(u) : "f"(v));
    return u;
}
__device__ __forceinline__ void mma_tf32(float c[4], const uint32_t a[4], uint32_t b0, uint32_t b1) {
    asm volatile(
        "mma.sync.aligned.m16n8k8.row.col.f32.tf32.tf32.f32 "
        "{%0,%1,%2,%3}, {%4,%5,%6,%7}, {%8,%9}, {%0,%1,%2,%3};"
        : "+f"(c[0]), "+f"(c[1]), "+f"(c[2]), "+f"(c[3])
        : "r"(a[0]), "r"(a[1]), "r"(a[2]), "r"(a[3]), "r"(b0), "r"(b1));
}

// ============================================================================
// Fused prep: blocks [0,128) convert W -> tf32 hi/lo images;
// blocks [128, 128+nb) init g_deg = 1 (self-loop pre-counted); block 128 also
// zeroes g_bsum (scan state).
// ============================================================================
__global__ void prep_kernel(const float* __restrict__ W1, const float* __restrict__ W2, int n) {
    int b = blockIdx.x, t = threadIdx.x;
    if (b < 128) {
        int idx = b * 256 + t;                 // 0..32767
        int layer = idx >> 14;
        int e = idx & 16383;                   // k*128 + n (coalesced read)
        int k = e >> 7, nn = e & 127;
        float v = (layer ? W2 : W1)[e];
        uint32_t hi = f2tf32(v);
        float lo_f = v - __uint_as_float(hi);
        uint32_t lo = f2tf32(lo_f);
        g_whi[layer][k * WS_STRIDE + nn] = __uint_as_float(hi);
        g_wlo[layer][k * WS_STRIDE + nn] = __uint_as_float(lo);
    } else {
        int i = (b - 128) * 256 + t;
        if (i < n) g_deg[i] = 1;               // self loop
        if (b == 128) g_bsum[t] = 0;
    }
}

// ============================================================================
// CSR build
// ============================================================================
__global__ void count_deg_kernel(const int* __restrict__ ei, int E) {
    int i = blockIdx.x * blockDim.x + threadIdx.x;
    if (i < E) atomicAdd(&g_deg[ei[E + i]], 1);
}

// Single-kernel exclusive scan (publish + lookback). All blocks publish before
// spinning; 196 tiny blocks are all co-resident -> deadlock-free.
__global__ void scan_rowptr_kernel(int n) {
    __shared__ int sh[256];
    __shared__ int red[256];
    int t = threadIdx.x, b = blockIdx.x;
    int i = b * 256 + t;
    int v = (i < n) ? g_deg[i] : 0;
    sh[t] = v;
    __syncthreads();
    for (int o = 1; o < 256; o <<= 1) {         // Hillis-Steele inclusive
        int u = (t >= o) ? sh[t - o] : 0;
        __syncthreads();
        sh[t] += u;
        __syncthreads();
    }
    if (t == 255) atomicExch(&g_bsum[b], sh[255] + SCAN_FLAG);
    // lookback: lane-parallel poll of all predecessor aggregates
    int agg = 0;
    for (int p = t; p < b; p += 256) {
        int val;
        do { val = *(volatile int*)&g_bsum[p]; } while (val < SCAN_FLAG);
        agg += val - SCAN_FLAG;
    }
    red[t] = agg;
    __syncthreads();
    for (int o = 128; o; o >>= 1) {
        if (t < o) red[t] += red[t + o];
        __syncthreads();
    }
    int excl = red[0] + sh[t] - v;
    if (i < n) {
        g_rowptr[i] = excl;
        g_cursor[i] = excl;
        if (i == n - 1) g_rowptr[n] = excl + v;
    }
}

__global__ void scatter_edges_kernel(const int* __restrict__ ei, int E, int n) {
    int i = blockIdx.x * blockDim.x + threadIdx.x;
    if (i < E) {
        int s = ei[i];
        int d = ei[E + i];
        g_csrsrc[atomicAdd(&g_cursor[d], 1)] = s;
    } else if (i < E + n) {
        int v = i - E;
        g_csrsrc[atomicAdd(&g_cursor[v], 1)] = v;   // self loop
    }
}

// ============================================================================
// Tensor-core GEMM + attention: XL = X @ W via tf32-split mma.sync (3 passes),
// fused a_s/a_d epilogue. CTA = 128 rows, 8 warps (16 rows/warp).
// ============================================================================
constexpr uint32_t SMEM_FLOATS = 128 * XS_STRIDE + 2 * WIMG;   // 51712
constexpr uint32_t SMEM_BYTES  = SMEM_FLOATS * 4;              // 206848

__global__ __launch_bounds__(256) void gemm_mma_kernel(
    const float* __restrict__ X,
    const float* __restrict__ Whi, const float* __restrict__ Wlo,
    const float* __restrict__ atts, const float* __restrict__ attd,
    float* __restrict__ XL, int n)
{
    extern __shared__ float sm[];
    float* Xs = sm;                       // 128 x 132
    float* Wh = sm + 128 * XS_STRIDE;     // 128 x 136
    float* Wl = Wh + WIMG;

    int tid = threadIdx.x, lane = tid & 31, warp = tid >> 5;
    int gid = lane >> 2, tig = lane & 3;
    int row0 = blockIdx.x * 128;

    // W tiles: linear float4 copies of the padded images (L2-broadcast across CTAs)
    {
        const float4* gh = (const float4*)Whi;
        const float4* gl = (const float4*)Wlo;
        float4* sh = (float4*)Wh;
        float4* sl = (float4*)Wl;
#pragma unroll
        for (int i = 0; i < 17; i++) {
            int idx = tid + i * 256;
            if (idx < WIMG / 4) { sh[idx] = gh[idx]; sl[idx] = gl[idx]; }
        }
    }
    // X tile: coalesced float4 loads, padded-stride stores
    {
        const float4* X4 = (const float4*)X;
#pragma unroll
        for (int i = 0; i < 16; i++) {
            int idx = tid + i * 256;        // 128 rows x 32 float4
            int r = idx >> 5, c = idx & 31;
            float4 v = make_float4(0.f, 0.f, 0.f, 0.f);
            if (row0 + r < n) v = X4[(size_t)(row0 + r) * 32 + c];
            *(float4*)(Xs + r * XS_STRIDE + c * 4) = v;
        }
    }
    __syncthreads();

    const int rbase = warp * 16;
    float c[16][4];
#pragma unroll
    for (int nt = 0; nt < 16; nt++) { c[nt][0] = c[nt][1] = c[nt][2] = c[nt][3] = 0.f; }

    const float* xr0 = Xs + (rbase + gid) * XS_STRIDE + tig;
    const float* xr1 = xr0 + 8 * XS_STRIDE;

    for (int ks = 0; ks < 16; ks++) {
        int k0 = ks * 8;
        float x0 = xr0[k0], x1 = xr1[k0], x2 = xr0[k0 + 4], x3 = xr1[k0 + 4];
        uint32_t ah[4], al[4];
        ah[0] = f2tf32(x0); al[0] = f2tf32(x0 - __uint_as_float(ah[0]));
        ah[1] = f2tf32(x1); al[1] = f2tf32(x1 - __uint_as_float(ah[1]));
        ah[2] = f2tf32(x2); al[2] = f2tf32(x2 - __uint_as_float(ah[2]));
        ah[3] = f2tf32(x3); al[3] = f2tf32(x3 - __uint_as_float(ah[3]));

        const float* wh0 = Wh + (k0 + tig) * WS_STRIDE + gid;
        const float* wl0 = Wl + (k0 + tig) * WS_STRIDE + gid;
#pragma unroll
        for (int nt = 0; nt < 16; nt++) {
            int nb = nt * 8;
            uint32_t bh0 = __float_as_uint(wh0[nb]);
            uint32_t bh1 = __float_as_uint(wh0[nb + 4 * WS_STRIDE]);
            uint32_t bl0 = __float_as_uint(wl0[nb]);
            uint32_t bl1 = __float_as_uint(wl0[nb + 4 * WS_STRIDE]);
            mma_tf32(c[nt], ah, bh0, bh1);
            mma_tf32(c[nt], ah, bl0, bl1);
            mma_tf32(c[nt], al, bh0, bh1);
        }
    }

    // Epilogue: attention dots + stores.
    float ps0 = 0.f, pd0 = 0.f, ps1 = 0.f, pd1 = 0.f;
#pragma unroll
    for (int nt = 0; nt < 16; nt++) {
        int col = nt * 8 + tig * 2;
        float a0 = __ldg(atts + col), a1 = __ldg(atts + col + 1);
        float d0 = __ldg(attd + col), d1 = __ldg(attd + col + 1);
        ps0 = fmaf(c[nt][0], a0, fmaf(c[nt][1], a1, ps0));
        pd0 = fmaf(c[nt][0], d0, fmaf(c[nt][1], d1, pd0));
        ps1 = fmaf(c[nt][2], a0, fmaf(c[nt][3], a1, ps1));
        pd1 = fmaf(c[nt][2], d0, fmaf(c[nt][3], d1, pd1));
    }
#pragma unroll
    for (int o = 1; o <= 2; o <<= 1) {
        ps0 += __shfl_xor_sync(0xffffffffu, ps0, o);
        pd0 += __shfl_xor_sync(0xffffffffu, pd0, o);
        ps1 += __shfl_xor_sync(0xffffffffu, ps1, o);
        pd1 += __shfl_xor_sync(0xffffffffu, pd1, o);
    }
    int r0 = row0 + rbase + gid;
    int r1 = r0 + 8;
    if (tig == 0) {
        if (r0 < n) { g_as[r0] = ps0; g_ad[r0] = pd0; }
        if (r1 < n) { g_as[r1] = ps1; g_ad[r1] = pd1; }
    }
    if (r0 < n) {
        float* dst = XL + (size_t)r0 * 128 + tig * 2;
#pragma unroll
        for (int nt = 0; nt < 16; nt++)
            *(float2*)(dst + nt * 8) = make_float2(c[nt][0], c[nt][1]);
    }
    if (r1 < n) {
        float* dst = XL + (size_t)r1 * 128 + tig * 2;
#pragma unroll
        for (int nt = 0; nt < 16; nt++)
            *(float2*)(dst + nt * 8) = make_float2(c[nt][2], c[nt][3]);
    }
}

// ============================================================================
// Aggregation (softmax weight inlined): one warp per dst node.
//   w_e = exp(leakyrelu(a_s[src_e] + a_d[v]))
//   out[v] = relu( (sum_e w_e * XL[src_e]) / (sum_e w_e + 1e-16) + b )
// Warp-uniform (src, a_s) loads; 4x unrolled for MLP.
// ============================================================================
__device__ __forceinline__ float edge_w(float as_v, float adv) {
    float t = as_v + adv;
    t = t > 0.f ? t : 0.2f * t;
    return __expf(t);
}

__global__ __launch_bounds__(256) void aggregate_kernel(
    const float* __restrict__ XL, const float* __restrict__ bias,
    float* __restrict__ OUT, int n)
{
    int wid = blockIdx.x * 8 + (threadIdx.x >> 5);
    int lane = threadIdx.x & 31;
    if (wid >= n) return;

    int beg = g_rowptr[wid];
    int end = g_rowptr[wid + 1];
    float adv = g_ad[wid];
    float4 acc = make_float4(0.f, 0.f, 0.f, 0.f);
    float z = 0.f;
    const float4* XL4 = (const float4*)XL;

    int j = beg;
    for (; j + 4 <= end; j += 4) {
        int s0 = g_csrsrc[j],     s1 = g_csrsrc[j + 1];
        int s2 = g_csrsrc[j + 2], s3 = g_csrsrc[j + 3];
        float w0 = edge_w(g_as[s0], adv);
        float w1 = edge_w(g_as[s1], adv);
        float w2 = edge_w(g_as[s2], adv);
        float w3 = edge_w(g_as[s3], adv);
        float4 x0 = XL4[(size_t)s0 * 32 + lane];
        float4 x1 = XL4[(size_t)s1 * 32 + lane];
        float4 x2 = XL4[(size_t)s2 * 32 + lane];
        float4 x3 = XL4[(size_t)s3 * 32 + lane];
        acc.x = fmaf(w0, x0.x, acc.x); acc.y = fmaf(w0, x0.y, acc.y);
        acc.z = fmaf(w0, x0.z, acc.z); acc.w = fmaf(w0, x0.w, acc.w);
        acc.x = fmaf(w1, x1.x, acc.x); acc.y = fmaf(w1, x1.y, acc.y);
        acc.z = fmaf(w1, x1.z, acc.z); acc.w = fmaf(w1, x1.w, acc.w);
        acc.x = fmaf(w2, x2.x, acc.x); acc.y = fmaf(w2, x2.y, acc.y);
        acc.z = fmaf(w2, x2.z, acc.z); acc.w = fmaf(w2, x2.w, acc.w);
        acc.x = fmaf(w3, x3.x, acc.x); acc.y = fmaf(w3, x3.y, acc.y);
        acc.z = fmaf(w3, x3.z, acc.z); acc.w = fmaf(w3, x3.w, acc.w);
        z += (w0 + w1) + (w2 + w3);
    }
    for (; j < end; j++) {
        int s = g_csrsrc[j];
        float w = edge_w(g_as[s], adv);
        float4 xv = XL4[(size_t)s * 32 + lane];
        acc.x = fmaf(w, xv.x, acc.x); acc.y = fmaf(w, xv.y, acc.y);
        acc.z = fmaf(w, xv.z, acc.z); acc.w = fmaf(w, xv.w, acc.w);
        z += w;
    }

    float inv = 1.f / (z + 1e-16f);
    float4 bv = ((const float4*)bias)[lane];
    float4 o;
    o.x = fmaxf(fmaf(acc.x, inv, bv.x), 0.f);
    o.y = fmaxf(fmaf(acc.y, inv, bv.y), 0.f);
    o.z = fmaxf(fmaf(acc.z, inv, bv.z), 0.f);
    o.w = fmaxf(fmaf(acc.w, inv, bv.w), 0.f);
    ((float4*)OUT)[(size_t)wid * 32 + lane] = o;
}

// ============================================================================
// Launch (8 kernels)
// ============================================================================
extern "C" void kernel_launch(void* const* d_in, const int* in_sizes, int n_in,
                              void* d_out, int out_size)
{
    const float* x   = (const float*)d_in[0];
    const int*   ei  = (const int*)d_in[1];
    const float* W1  = (const float*)d_in[2];
    const float* as1 = (const float*)d_in[3];
    const float* ad1 = (const float*)d_in[4];
    const float* b1  = (const float*)d_in[5];
    const float* W2  = (const float*)d_in[6];
    const float* as2 = (const float*)d_in[7];
    const float* ad2 = (const float*)d_in[8];
    const float* b2  = (const float*)d_in[9];

    int n = in_sizes[0] / DDIM;   // 50000
    int E = in_sizes[1] / 2;      // 800000
    int ee = E + n;
    float* out = (float*)d_out;

    void *xl_p, *h_p, *wh_p, *wl_p;
    cudaGetSymbolAddress(&xl_p, g_xl);
    cudaGetSymbolAddress(&h_p,  g_h);
    cudaGetSymbolAddress(&wh_p, g_whi);
    cudaGetSymbolAddress(&wl_p, g_wlo);
    float* xl = (float*)xl_p;
    float* h  = (float*)h_p;
    const float* whi = (const float*)wh_p;
    const float* wlo = (const float*)wl_p;

    cudaFuncSetAttribute(gemm_mma_kernel, cudaFuncAttributeMaxDynamicSharedMemorySize, SMEM_BYTES);

    int nb = (n + 255) / 256;     // 196

    // --- prep (W images + deg=1 init + scan-state zero) & CSR build ---
    prep_kernel<<<128 + nb, 256>>>(W1, W2, n);
    count_deg_kernel<<<(E + 255) / 256, 256>>>(ei, E);
    scan_rowptr_kernel<<<nb, 256>>>(n);
    scatter_edges_kernel<<<(ee + 255) / 256, 256>>>(ei, E, n);

    int gblocks = (n + 127) / 128;

    // --- Layer 1 ---
    gemm_mma_kernel<<<gblocks, 256, SMEM_BYTES>>>(x, whi, wlo, as1, ad1, xl, n);
    aggregate_kernel<<<(n + 7) / 8, 256>>>(xl, b1, h, n);

    // --- Layer 2 ---
    gemm_mma_kernel<<<gblocks, 256, SMEM_BYTES>>>(h, whi + WIMG, wlo + WIMG, as2, ad2, xl, n);
    aggregate_kernel<<<(n + 7) / 8, 256>>>(xl, b2, out, n);
}